// round 1
// baseline (speedup 1.0000x reference)
#include <cuda_runtime.h>
#include <math.h>

#define NQ 6
#define NL 4
#define NA 4
#define PRE 64
#define NS 64   // 2^NQ amplitudes

__global__ void __launch_bounds__(256) qpolicy_kernel(
    const float* __restrict__ x,
    const float* __restrict__ W1, const float* __restrict__ b1,
    const float* __restrict__ W2, const float* __restrict__ b2,
    const float* __restrict__ qw,
    const float* __restrict__ Wp, const float* __restrict__ bp,
    const float* __restrict__ Wv, const float* __restrict__ bv,
    float* __restrict__ out_policy, float* __restrict__ out_value,
    int B)
{
    __shared__ float sW1[PRE * NQ];
    __shared__ float sb1[PRE];
    __shared__ float sW2[NQ * PRE];
    __shared__ float sb2[NQ];
    __shared__ float sqc[NL * NQ];
    __shared__ float sqs[NL * NQ];
    __shared__ float sWp[NA * NQ];
    __shared__ float sbp[NA];
    __shared__ float sWv[NQ];
    __shared__ float sbv;

    const int tid = threadIdx.x;
    for (int i = tid; i < PRE * NQ; i += blockDim.x) sW1[i] = W1[i];
    for (int i = tid; i < PRE; i += blockDim.x)      sb1[i] = b1[i];
    for (int i = tid; i < NQ * PRE; i += blockDim.x) sW2[i] = W2[i];
    if (tid < NQ) sb2[tid] = b2[tid];
    if (tid < NL * NQ) {
        float h = 0.5f * qw[tid];
        sqc[tid] = cosf(h);
        sqs[tid] = sinf(h);
    }
    if (tid < NA * NQ) sWp[tid] = Wp[tid];
    if (tid < NA)      sbp[tid] = bp[tid];
    if (tid < NQ)      sWv[tid] = Wv[tid];
    if (tid == 0)      sbv = bv[0];
    __syncthreads();

    const int b = blockIdx.x * blockDim.x + tid;
    if (b >= B) return;

    // ---------------- pre-net: xp = relu(relu(x@W1^T + b1) @ W2^T + b2) -----
    float xi[NQ];
#pragma unroll
    for (int q = 0; q < NQ; ++q) xi[q] = x[(size_t)b * NQ + q];

    float xp[NQ];
#pragma unroll
    for (int j = 0; j < NQ; ++j) xp[j] = sb2[j];

#pragma unroll 8
    for (int k = 0; k < PRE; ++k) {
        float h = sb1[k];
#pragma unroll
        for (int q = 0; q < NQ; ++q) h = fmaf(sW1[k * NQ + q], xi[q], h);
        h = fmaxf(h, 0.0f);
#pragma unroll
        for (int j = 0; j < NQ; ++j) xp[j] = fmaf(sW2[j * PRE + k], h, xp[j]);
    }
#pragma unroll
    for (int j = 0; j < NQ; ++j) xp[j] = fmaxf(xp[j], 0.0f);

    // ---------------- angle embedding: state = outer product of (c,s) -------
    // qubit q <-> bit q (LSB). Internal bit convention is free: final z_q
    // depends only on per-qubit marginals, and RY/CNOT/measure all use the
    // same mapping.
    float ec[NQ], es[NQ];
#pragma unroll
    for (int q = 0; q < NQ; ++q) {
        float h = 0.5f * xp[q];
        ec[q] = cosf(h);
        es[q] = sinf(h);
    }

    float st[NS];
    st[0] = ec[0];
    st[1] = es[0];
#pragma unroll
    for (int q = 1; q < NQ; ++q) {
        const int sz = 1 << q;
#pragma unroll
        for (int i = 0; i < NS; ++i) {
            if (i < sz) {
                st[i | sz] = st[i] * es[q];
                st[i]      = st[i] * ec[q];
            }
        }
    }

    // ---------------- 4 entangling layers ----------------------------------
#pragma unroll
    for (int l = 0; l < NL; ++l) {
        // CNOT ring: control i -> target (i+1)%NQ. Compile-time permutation.
#pragma unroll
        for (int i = 0; i < NQ; ++i) {
            const int cb = 1 << i;
            const int tb = 1 << ((i + 1) % NQ);
#pragma unroll
            for (int idx = 0; idx < NS; ++idx) {
                if ((idx & cb) && !(idx & tb)) {
                    float tmp = st[idx];
                    st[idx] = st[idx | tb];
                    st[idx | tb] = tmp;
                }
            }
        }
        // fixed-angle RY on each qubit
#pragma unroll
        for (int i = 0; i < NQ; ++i) {
            const float c = sqc[l * NQ + i];
            const float s = sqs[l * NQ + i];
            const int qb = 1 << i;
#pragma unroll
            for (int idx = 0; idx < NS; ++idx) {
                if (!(idx & qb)) {
                    const int j = idx | qb;
                    const float a0 = st[idx];
                    const float a1 = st[j];
                    st[idx] = fmaf(c, a0, -s * a1);
                    st[j]   = fmaf(s, a0,  c * a1);
                }
            }
        }
    }

    // ---------------- measurement: z_q = <Z_q> ------------------------------
    float z[NQ];
#pragma unroll
    for (int q = 0; q < NQ; ++q) z[q] = 0.0f;
#pragma unroll
    for (int idx = 0; idx < NS; ++idx) {
        const float p = st[idx] * st[idx];
#pragma unroll
        for (int q = 0; q < NQ; ++q) {
            if ((idx >> q) & 1) z[q] -= p;
            else                z[q] += p;
        }
    }

    // ---------------- heads -------------------------------------------------
    float logits[NA];
#pragma unroll
    for (int a = 0; a < NA; ++a) {
        float L = sbp[a];
#pragma unroll
        for (int q = 0; q < NQ; ++q) L = fmaf(sWp[a * NQ + q], z[q], L);
        logits[a] = L;
    }
    float m = logits[0];
#pragma unroll
    for (int a = 1; a < NA; ++a) m = fmaxf(m, logits[a]);
    float e[NA], sum = 0.0f;
#pragma unroll
    for (int a = 0; a < NA; ++a) { e[a] = expf(logits[a] - m); sum += e[a]; }
    const float inv = 1.0f / sum;

    float4 pol;
    pol.x = e[0] * inv;
    pol.y = e[1] * inv;
    pol.z = e[2] * inv;
    pol.w = e[3] * inv;
    reinterpret_cast<float4*>(out_policy)[b] = pol;

    float val = sbv;
#pragma unroll
    for (int q = 0; q < NQ; ++q) val = fmaf(sWv[q], z[q], val);
    out_value[b] = val;
}

extern "C" void kernel_launch(void* const* d_in, const int* in_sizes, int n_in,
                              void* d_out, int out_size) {
    const float* x  = (const float*)d_in[0];
    const float* W1 = (const float*)d_in[1];
    const float* b1 = (const float*)d_in[2];
    const float* W2 = (const float*)d_in[3];
    const float* b2 = (const float*)d_in[4];
    const float* qw = (const float*)d_in[5];
    const float* Wp = (const float*)d_in[6];
    const float* bp = (const float*)d_in[7];
    const float* Wv = (const float*)d_in[8];
    const float* bv = (const float*)d_in[9];

    const int B = in_sizes[0] / NQ;
    float* out_policy = (float*)d_out;            // (B, NA) row-major
    float* out_value  = (float*)d_out + (size_t)B * NA;  // (B,)

    const int threads = 256;
    const int blocks = (B + threads - 1) / threads;
    qpolicy_kernel<<<blocks, threads>>>(x, W1, b1, W2, b2, qw, Wp, bp, Wv, bv,
                                        out_policy, out_value, B);
}